// round 17
// baseline (speedup 1.0000x reference)
#include <cuda_runtime.h>
#include <cuda_fp16.h>
#include <math.h>
#include <stdint.h>

#define Bb   4
#define SS   1024
#define DD   1024
#define HH   16
#define HKK  8
#define HDD  64
#define FFF  3072
#define LL   4
#define NTOK (Bb*SS)
#define WIN_ 12

// ---------------- scratch (device globals; no allocations allowed) -----------
__device__ float g_h [(size_t)NTOK*DD];
// fp16 activation planes
__device__ __half g_nh[(size_t)NTOK*DD];
__device__ __half g_ch[(size_t)NTOK*DD];
__device__ __half g_ah[(size_t)NTOK*FFF];
// fp16 attention operand planes
__device__ __half g_qh[(size_t)Bb*HH*SS*HDD];
__device__ __half g_kh[(size_t)Bb*HKK*SS*HDD];
__device__ __half g_vh[(size_t)Bb*HKK*SS*HDD];

// fp16 weights in native [K][N] layout; per-layer element offsets (halves):
//  qkv: [1024][2048] (wq|wk|wv cols)   @0
//  wo : [1024][1024]                    @2097152
//  gu : [1024][6144] interleaved g/u    @3145728
//  dn : [3072][1024]                    @9437184
#define W1_QKV   0
#define W1_WO    2097152
#define W1_GU    3145728
#define W1_DN    9437184
#define W1_LAYER 12582912
__device__ __half g_wt[(size_t)LL*W1_LAYER];

// ---------------- helpers -----------------------------------------------------
__device__ __forceinline__ uint32_t smem_u32(const void* p){
    uint32_t a;
    asm("{ .reg .u64 t; cvta.to.shared.u64 t, %1; cvt.u32.u64 %0, t; }" : "=r"(a) : "l"(p));
    return a;
}
__device__ __forceinline__ uint32_t packh(__half a, __half b){
    __half2 t(a, b);
    return *(uint32_t*)&t;
}
__device__ __forceinline__ uint32_t f22h(float a, float b){
    __half2 t = __floats2half2_rn(a, b);
    return *(uint32_t*)&t;
}
__device__ __forceinline__ uint2 pack4h(float4 v){
    return make_uint2(packh(__float2half_rn(v.x), __float2half_rn(v.y)),
                      packh(__float2half_rn(v.z), __float2half_rn(v.w)));
}

#define LDSM4(r, addr) \
    asm volatile("ldmatrix.sync.aligned.m8n8.x4.shared.b16 {%0,%1,%2,%3}, [%4];" \
        : "=r"((r)[0]), "=r"((r)[1]), "=r"((r)[2]), "=r"((r)[3]) : "r"(addr))

#define LDSM4T(r, addr) \
    asm volatile("ldmatrix.sync.aligned.m8n8.x4.trans.shared.b16 {%0,%1,%2,%3}, [%4];" \
        : "=r"((r)[0]), "=r"((r)[1]), "=r"((r)[2]), "=r"((r)[3]) : "r"(addr))

#define MMA16816(c, a, b0, b1) \
    asm volatile("mma.sync.aligned.m16n8k16.row.col.f32.f16.f16.f32 " \
        "{%0,%1,%2,%3}, {%4,%5,%6,%7}, {%8,%9}, {%0,%1,%2,%3};" \
        : "+f"((c)[0]), "+f"((c)[1]), "+f"((c)[2]), "+f"((c)[3]) \
        : "r"((a)[0]), "r"((a)[1]), "r"((a)[2]), "r"((a)[3]), "r"(b0), "r"(b1))

#define CPASYNC16(dst, src) \
    asm volatile("cp.async.cg.shared.global [%0], [%1], 16;" \
        :: "r"(dst), "l"((unsigned long long)__cvta_generic_to_global(src)))

// ============ GEMM: C[M,N] (+)= A[M,K] * B[K,N], fp16 in / fp32 acc ==========
// CTA tile 128x128, BK=32/stage, 3 stages, ONE sync/iter, 256 threads.
// A [M][K] via LDSM4; B [K][N] row-major via LDSM4T (pattern = attn V path).
// EP=0: fp32 C (+=ACC).  EP=1: interleaved gate/up -> silu(g)*u fp16 Ch.
// EP=2: fused QK-RMSNorm+RoPE epilogue -> q/k/v fp16 planes.
template<int ACC, int EP>
__global__ void __launch_bounds__(256, 2) gemm_mma(
        const __half* __restrict__ A, const __half* __restrict__ Bt, int ldb,
        float* __restrict__ C, __half* __restrict__ Ch, int K, int N,
        const float* __restrict__ qw, const float* __restrict__ kw,
        __half* __restrict__ qp, __half* __restrict__ kp, __half* __restrict__ vp){
    __shared__ __align__(16) __half smg[3*8192];
    const int tid = threadIdx.x, lane = tid & 31, wid = tid >> 5;
    const int wm = (wid >> 1) << 5, wn = (wid & 1) << 6;
    const int bm = blockIdx.y << 7, bn = blockIdx.x << 7;
    const uint32_t sb = smem_u32(smg);

    float c[2][8][4];
    #pragma unroll
    for(int i = 0; i < 2; i++)
        #pragma unroll
        for(int j = 0; j < 8; j++){
            c[i][j][0] = 0.f; c[i][j][1] = 0.f; c[i][j][2] = 0.f; c[i][j][3] = 0.f;
        }

    auto prefetch = [&](int s, int kt){
        #pragma unroll
        for(int j = 0; j < 2; j++){
            int cid = (tid << 1) | j;
            // A region: 128 rows x 4 chunks (row = 32 halves)
            int rowA = cid >> 2, chA = cid & 3;
            CPASYNC16(sb + 2u * (uint32_t)(s * 8192 + rowA * 32 +
                      ((chA ^ ((rowA >> 1) & 3)) << 3)),
                      A + (size_t)(bm + rowA) * K + kt * 32 + (chA << 3));
            // B region: 32 rows x 16 chunks (row = 128 halves = 256B)
            int rowB = cid >> 4, chB = cid & 15;
            int physB = (chB & 8) | ((chB ^ rowB) & 7);
            CPASYNC16(sb + 2u * (uint32_t)(s * 8192 + 4096 + rowB * 128 + (physB << 3)),
                      Bt + (size_t)(kt * 32 + rowB) * ldb + bn + (chB << 3));
        }
    };

    const int T = K >> 5;
    prefetch(0, 0);
    asm volatile("cp.async.commit_group;");
    prefetch(1, 1);
    asm volatile("cp.async.commit_group;");

    for(int kt = 0; kt < T; kt++){
        const int s = kt % 3;
        if(kt + 1 < T) asm volatile("cp.async.wait_group 1;");
        else           asm volatile("cp.async.wait_group 0;");
        __syncthreads();
        if(kt + 2 < T){
            prefetch((kt + 2) % 3, kt + 2);
            asm volatile("cp.async.commit_group;");
        }
        const uint32_t stg = sb + 2u * (uint32_t)(s * 8192);
        #pragma unroll
        for(int kk = 0; kk < 2; kk++){
            uint32_t a[2][4];
            #pragma unroll
            for(int mt = 0; mt < 2; mt++){
                int R = wm + mt * 16 + (lane & 15);
                int phys = (kk * 2 + (lane >> 4)) ^ ((R >> 1) & 3);
                LDSM4(a[mt], stg + 2u * (uint32_t)(R * 32 + (phys << 3)));
            }
            #pragma unroll
            for(int ng = 0; ng < 4; ng++){
                int R  = kk * 16 + (((lane >> 3) & 1) << 3) + (lane & 7);
                int ch = (wn >> 3) + (ng << 1) + (lane >> 4);
                int phys = (ch & 8) | ((ch ^ (R & 7)) & 7);
                uint32_t b[4];
                LDSM4T(b, stg + 2u * (uint32_t)(4096 + R * 128 + (phys << 3)));
                #pragma unroll
                for(int mt = 0; mt < 2; mt++){
                    MMA16816(c[mt][2*ng],   a[mt], b[0], b[1]);
                    MMA16816(c[mt][2*ng+1], a[mt], b[2], b[3]);
                }
            }
        }
    }

    // ---- epilogues ----
    if(EP == 2){
        const int hidx = (bn + wn) >> 6;     // 0..15 q, 16..23 k, 24..31 v
        #pragma unroll
        for(int mt = 0; mt < 2; mt++){
            #pragma unroll
            for(int half = 0; half < 2; half++){
                const int token = bm + wm + mt * 16 + (lane >> 2) + half * 8;
                const int jb = half << 1;
                const int bb = token >> 10, sp = token & (SS - 1);
                __half* dst;
                if(hidx < 16)      dst = qp + (((size_t)bb*HH  + hidx)      * SS + sp) * HDD;
                else if(hidx < 24) dst = kp + (((size_t)bb*HKK + hidx - 16) * SS + sp) * HDD;
                else               dst = vp + (((size_t)bb*HKK + hidx - 24) * SS + sp) * HDD;
                if(hidx >= 24){
                    #pragma unroll
                    for(int nt = 0; nt < 8; nt++){
                        int d = nt * 8 + ((lane & 3) << 1);
                        *(uint32_t*)&dst[d] = f22h(c[mt][nt][jb], c[mt][nt][jb+1]);
                    }
                } else {
                    const float* wn2 = (hidx < 16) ? qw : kw;
                    float ssq = 0.f;
                    #pragma unroll
                    for(int nt = 0; nt < 8; nt++)
                        ssq += c[mt][nt][jb]*c[mt][nt][jb] + c[mt][nt][jb+1]*c[mt][nt][jb+1];
                    ssq += __shfl_xor_sync(~0u, ssq, 1);
                    ssq += __shfl_xor_sync(~0u, ssq, 2);
                    float rn = rsqrtf(ssq * (1.f/64.f) + 1e-6f);
                    float scq = (hidx < 16) ? 0.125f : 1.f;
                    #pragma unroll
                    for(int nt = 0; nt < 4; nt++){
                        float yl[2], yh[2];
                        #pragma unroll
                        for(int e = 0; e < 2; e++){
                            int d = nt * 8 + ((lane & 3) << 1) + e;
                            float x0 = c[mt][nt][jb+e]   * rn * wn2[d];
                            float x1 = c[mt][nt+4][jb+e] * rn * wn2[d+32];
                            float ang = (float)sp * expf(-(float)d * 0.431734704963f);
                            float sn, cs; sincosf(ang, &sn, &cs);
                            yl[e] = (x0 * cs - x1 * sn) * scq;
                            yh[e] = (x1 * cs + x0 * sn) * scq;
                        }
                        int d0 = nt * 8 + ((lane & 3) << 1);
                        *(uint32_t*)&dst[d0]    = f22h(yl[0], yl[1]);
                        *(uint32_t*)&dst[d0+32] = f22h(yh[0], yh[1]);
                    }
                }
            }
        }
        return;
    }
    #pragma unroll
    for(int mt = 0; mt < 2; mt++)
        #pragma unroll
        for(int nt = 0; nt < 8; nt++){
            int r  = bm + wm + mt * 16 + (lane >> 2);
            int cc = bn + wn + nt * 8 + ((lane & 3) << 1);
            if(EP == 1){
                int j = cc >> 1;
                float g0 = c[mt][nt][0], u0 = c[mt][nt][1];
                float g1 = c[mt][nt][2], u1 = c[mt][nt][3];
                float o0 = g0 / (1.f + expf(-g0)) * u0;
                float o1 = g1 / (1.f + expf(-g1)) * u1;
                Ch[(size_t)r * (N >> 1) + j]       = __float2half_rn(o0);
                Ch[(size_t)(r + 8) * (N >> 1) + j] = __float2half_rn(o1);
            } else {
                float* p0 = C + (size_t)r * N + cc;
                float* p1 = C + (size_t)(r + 8) * N + cc;
                float2 v0 = make_float2(c[mt][nt][0], c[mt][nt][1]);
                float2 v1 = make_float2(c[mt][nt][2], c[mt][nt][3]);
                if(ACC){
                    float2 o = *(const float2*)p0; v0.x += o.x; v0.y += o.y;
                    o = *(const float2*)p1;        v1.x += o.x; v1.y += o.y;
                }
                *(float2*)p0 = v0;
                *(float2*)p1 = v1;
            }
        }
}

// ---------------- weight converters (native layout, coalesced) ---------------
// plain: dst[l][i] = fp16(src[l][i]); i in float4 units
__global__ void conv_plain(const float* __restrict__ src, __half* __restrict__ dst,
                           int n4, size_t sls, size_t dls){
    int l = blockIdx.y;
    int i = blockIdx.x * blockDim.x + threadIdx.x;
    if(i >= n4) return;
    float4 v = ((const float4*)(src + (size_t)l * sls))[i];
    ((uint2*)(dst + (size_t)l * dls))[i] = pack4h(v);
}
// qkv: dst row = [wq(1024) | wk(512) | wv(512)] -> [1024][2048]
__global__ void conv_qkv(const float* __restrict__ wq, const float* __restrict__ wk,
                         const float* __restrict__ wv, __half* __restrict__ dst){
    int l = blockIdx.y;
    int i = blockIdx.x * blockDim.x + threadIdx.x;   // 0 .. 1024*512-1 (quads)
    int k = i >> 9, q = i & 511;
    int n = q << 2;
    const float* s;
    if(n < 1024)      s = wq + (size_t)l * 1048576 + k * 1024 + n;
    else if(n < 1536) s = wk + (size_t)l * 524288  + k * 512  + (n - 1024);
    else              s = wv + (size_t)l * 524288  + k * 512  + (n - 1536);
    float4 v = *(const float4*)s;
    ((uint2*)(dst + (size_t)l * W1_LAYER))[i] = pack4h(v);
}
// gate/up interleave: dst[k][2n]=g[k][n], dst[k][2n+1]=u[k][n] -> [1024][6144]
__global__ void conv_gu(const float* __restrict__ wg, const float* __restrict__ wu,
                        __half* __restrict__ dst){
    int l = blockIdx.y;
    int i = blockIdx.x * blockDim.x + threadIdx.x;   // 0 .. 1024*768-1
    int k = i / 768, t = i % 768;
    int n = t << 2;
    size_t so = (size_t)l * 3145728 + (size_t)k * 3072 + n;
    float4 g = *(const float4*)(wg + so);
    float4 u = *(const float4*)(wu + so);
    uint4 o = make_uint4(f22h(g.x, u.x), f22h(g.y, u.y), f22h(g.z, u.z), f22h(g.w, u.w));
    ((uint4*)(dst + (size_t)l * W1_LAYER))[i] = o;
}

// ---------------- RMSNorm over rows of width DD ------------------------------
template<int HF>
__global__ void rmsnorm_k(const float* __restrict__ x, const float* __restrict__ w,
                          float* __restrict__ out, __half* __restrict__ oh){
    int row = blockIdx.x;
    const float4* xr = (const float4*)(x + (size_t)row * DD);
    float4 v = xr[threadIdx.x];
    float ss = v.x*v.x + v.y*v.y + v.z*v.z + v.w*v.w;
    __shared__ float red[8];
    #pragma unroll
    for(int o = 16; o; o >>= 1) ss += __shfl_xor_sync(~0u, ss, o);
    if((threadIdx.x & 31) == 0) red[threadIdx.x >> 5] = ss;
    __syncthreads();
    if(threadIdx.x < 8){
        float t = red[threadIdx.x];
        #pragma unroll
        for(int o = 4; o; o >>= 1) t += __shfl_xor_sync(0xff, t, o);
        if(threadIdx.x == 0) red[0] = rsqrtf(t / (float)DD + 1e-6f);
    }
    __syncthreads();
    float r = red[0];
    float4 wv = ((const float4*)w)[threadIdx.x];
    float4 o4 = make_float4(v.x*r*wv.x, v.y*r*wv.y, v.z*r*wv.z, v.w*r*wv.w);
    if(HF){
        *(uint2*)&oh[(size_t)row * DD + (threadIdx.x << 2)] = pack4h(o4);
    } else {
        ((float4*)(out + (size_t)row * DD))[threadIdx.x] = o4;
    }
}

// ---------------- tensor-core flash attention --------------------------------
__global__ void __launch_bounds__(128) attn_mma(const int* __restrict__ amask,
                                                int win, __half* __restrict__ Ch){
    __shared__ __align__(16) __half Qs[4096];
    __shared__ __align__(16) __half Ks[2][4096];
    __shared__ __align__(16) __half Vs[2][4096];
    __shared__ int msk[64];
    const int b = blockIdx.z, h = blockIdx.y, q0 = blockIdx.x << 6;
    const int kvh = h >> 1;
    const int tid = threadIdx.x, lane = tid & 31, w = tid >> 5;
    const uint32_t sq = smem_u32(Qs);
    const uint32_t sk = smem_u32(Ks);
    const uint32_t sv = smem_u32(Vs);

    const __half* Qg = g_qh + (((size_t)b * HH + h) * SS + q0) * HDD;
    const __half* Kg = g_kh + ((size_t)b * HKK + kvh) * SS * HDD;
    const __half* Vg = g_vh + ((size_t)b * HKK + kvh) * SS * HDD;

    #pragma unroll
    for(int i = 0; i < 4; i++){
        int cid = tid + (i << 7);
        int row = cid >> 3, ch = cid & 7;
        CPASYNC16(sq + (uint32_t)(row * 128 + ((ch ^ (row & 7)) << 4)),
                  Qg + row * HDD + ch * 8);
    }
    const bool full = (win >= SS);
    int kbeg = 0, kend = SS;
    if(!full){ kbeg = max(0, q0 - win) & ~63; kend = min(SS, q0 + 63 + win + 1); }

    auto ldtile = [&](int s, int kt){
        #pragma unroll
        for(int i = 0; i < 4; i++){
            int cid = tid + (i << 7);
            int row = cid >> 3, ch = cid & 7;
            uint32_t off = (uint32_t)((s << 13) + row * 128 + ((ch ^ (row & 7)) << 4));
            CPASYNC16(sk + off, Kg + (size_t)(kt + row) * HDD + ch * 8);
            CPASYNC16(sv + off, Vg + (size_t)(kt + row) * HDD + ch * 8);
        }
    };
    ldtile(0, kbeg);
    asm volatile("cp.async.commit_group;");

    float o[8][4];
    #pragma unroll
    for(int i = 0; i < 8; i++){ o[i][0]=0.f; o[i][1]=0.f; o[i][2]=0.f; o[i][3]=0.f; }
    float m0 = -1e30f, m1 = -1e30f, l0 = 0.f, l1 = 0.f;
    uint32_t qa[4][4];

    const int nTiles = (kend - kbeg + 63) >> 6;
    for(int it = 0; it < nTiles; it++){
        const int kt = kbeg + (it << 6);
        const int s = it & 1;
        if(it + 1 < nTiles){
            ldtile(s ^ 1, kt + 64);
            asm volatile("cp.async.commit_group;");
            asm volatile("cp.async.wait_group 1;");
        } else {
            asm volatile("cp.async.wait_group 0;");
        }
        if(tid < 64) msk[tid] = amask[b * SS + kt + tid];
        __syncthreads();
        if(it == 0){
            #pragma unroll
            for(int kk = 0; kk < 4; kk++){
                int R = (w << 4) + (lane & 15);
                int ch = (kk << 1) + (lane >> 4);
                LDSM4(qa[kk], sq + (uint32_t)(R * 128 + ((ch ^ (R & 7)) << 4)));
            }
        }
        float sc[8][4];
        #pragma unroll
        for(int i = 0; i < 8; i++){ sc[i][0]=0.f; sc[i][1]=0.f; sc[i][2]=0.f; sc[i][3]=0.f; }
        const uint32_t skb = sk + (uint32_t)(s << 13);
        #pragma unroll
        for(int kk = 0; kk < 4; kk++){
            #pragma unroll
            for(int ng = 0; ng < 4; ng++){
                int R = (ng << 4) + (lane & 7) + ((lane >> 4) << 3);
                int ch = (kk << 1) + ((lane >> 3) & 1);
                uint32_t bk[4];
                LDSM4(bk, skb + (uint32_t)(R * 128 + ((ch ^ (R & 7)) << 4)));
                MMA16816(sc[2*ng],   qa[kk], bk[0], bk[1]);
                MMA16816(sc[2*ng+1], qa[kk], bk[2], bk[3]);
            }
        }
        const int qr0 = q0 + (w << 4) + (lane >> 2), qr1 = qr0 + 8;
        float mx0 = -1e30f, mx1 = -1e30f;
        #pragma unroll
        for(int nt = 0; nt < 8; nt++){
            int c0 = (nt << 3) + ((lane & 3) << 1);
            int j0 = kt + c0, j1 = j0 + 1;
            bool k0 = msk[c0] > 0, k1 = msk[c0 + 1] > 0;
            if(!(k0 && (full || abs(qr0 - j0) <= win))) sc[nt][0] = -1e30f;
            if(!(k1 && (full || abs(qr0 - j1) <= win))) sc[nt][1] = -1e30f;
            if(!(k0 && (full || abs(qr1 - j0) <= win))) sc[nt][2] = -1e30f;
            if(!(k1 && (full || abs(qr1 - j1) <= win))) sc[nt][3] = -1e30f;
            mx0 = fmaxf(mx0, fmaxf(sc[nt][0], sc[nt][1]));
            mx1 = fmaxf(mx1, fmaxf(sc[nt][2], sc[nt][3]));
        }
        mx0 = fmaxf(mx0, __shfl_xor_sync(~0u, mx0, 1));
        mx0 = fmaxf(mx0, __shfl_xor_sync(~0u, mx0, 2));
        mx1 = fmaxf(mx1, __shfl_xor_sync(~0u, mx1, 1));
        mx1 = fmaxf(mx1, __shfl_xor_sync(~0u, mx1, 2));
        float mn0 = fmaxf(m0, mx0), mn1 = fmaxf(m1, mx1);
        float cor0 = expf(m0 - mn0), cor1 = expf(m1 - mn1);
        float s0 = 0.f, s1 = 0.f;
        #pragma unroll
        for(int nt = 0; nt < 8; nt++){
            sc[nt][0] = (sc[nt][0] > -1e29f) ? expf(sc[nt][0] - mn0) : 0.f;
            sc[nt][1] = (sc[nt][1] > -1e29f) ? expf(sc[nt][1] - mn0) : 0.f;
            sc[nt][2] = (sc[nt][2] > -1e29f) ? expf(sc[nt][2] - mn1) : 0.f;
            sc[nt][3] = (sc[nt][3] > -1e29f) ? expf(sc[nt][3] - mn1) : 0.f;
            s0 += sc[nt][0] + sc[nt][1];
            s1 += sc[nt][2] + sc[nt][3];
        }
        s0 += __shfl_xor_sync(~0u, s0, 1); s0 += __shfl_xor_sync(~0u, s0, 2);
        s1 += __shfl_xor_sync(~0u, s1, 1); s1 += __shfl_xor_sync(~0u, s1, 2);
        l0 = l0 * cor0 + s0;  l1 = l1 * cor1 + s1;
        m0 = mn0;  m1 = mn1;
        #pragma unroll
        for(int nt = 0; nt < 8; nt++){
            o[nt][0] *= cor0; o[nt][1] *= cor0;
            o[nt][2] *= cor1; o[nt][3] *= cor1;
        }
        const uint32_t svb = sv + (uint32_t)(s << 13);
        #pragma unroll
        for(int kk = 0; kk < 4; kk++){
            uint32_t pa[4];
            pa[0] = f22h(sc[2*kk][0],   sc[2*kk][1]);
            pa[1] = f22h(sc[2*kk][2],   sc[2*kk][3]);
            pa[2] = f22h(sc[2*kk+1][0], sc[2*kk+1][1]);
            pa[3] = f22h(sc[2*kk+1][2], sc[2*kk+1][3]);
            #pragma unroll
            for(int hg = 0; hg < 4; hg++){
                int R = (kk << 4) + (((lane >> 3) & 1) << 3) + (lane & 7);
                int ch = (hg << 1) + (lane >> 4);
                uint32_t bv[4];
                LDSM4T(bv, svb + (uint32_t)(R * 128 + ((ch ^ (R & 7)) << 4)));
                MMA16816(o[2*hg],   pa, bv[0], bv[1]);
                MMA16816(o[2*hg+1], pa, bv[2], bv[3]);
            }
        }
        __syncthreads();
    }
    float i0 = (l0 > 0.f) ? 1.f / l0 : 0.f;
    float i1 = (l1 > 0.f) ? 1.f / l1 : 0.f;
    const int row0 = (b << 10) + q0 + (w << 4) + (lane >> 2);
    const int row1 = row0 + 8;
    #pragma unroll
    for(int nt = 0; nt < 8; nt++){
        int col = (h << 6) + (nt << 3) + ((lane & 3) << 1);
        *(uint32_t*)&Ch[(size_t)row0 * DD + col] = f22h(o[nt][0] * i0, o[nt][1] * i0);
        *(uint32_t*)&Ch[(size_t)row1 * DD + col] = f22h(o[nt][2] * i1, o[nt][3] * i1);
    }
}

// ---------------- driver -----------------------------------------------------
extern "C" void kernel_launch(void* const* d_in, const int* in_sizes, int n_in,
                              void* d_out, int out_size){
    const float* emb = (const float*)d_in[0];
    const float* wq  = (const float*)d_in[1];
    const float* wk  = (const float*)d_in[2];
    const float* wv  = (const float*)d_in[3];
    const float* wo  = (const float*)d_in[4];
    const float* qnw = (const float*)d_in[5];
    const float* knw = (const float*)d_in[6];
    const float* ln1 = (const float*)d_in[7];
    const float* ln2 = (const float*)d_in[8];
    const float* wg  = (const float*)d_in[9];
    const float* wu  = (const float*)d_in[10];
    const float* wd  = (const float*)d_in[11];
    const float* nw  = (const float*)d_in[12];
    const int*   am  = (const int*)d_in[13];

    float *p_h;
    __half *p_wt, *p_nh, *p_ch, *p_ah, *p_qh, *p_kh, *p_vh;
    cudaGetSymbolAddress((void**)&p_h,  g_h);
    cudaGetSymbolAddress((void**)&p_wt, g_wt);
    cudaGetSymbolAddress((void**)&p_nh, g_nh);
    cudaGetSymbolAddress((void**)&p_ch, g_ch);
    cudaGetSymbolAddress((void**)&p_ah, g_ah);
    cudaGetSymbolAddress((void**)&p_qh, g_qh);
    cudaGetSymbolAddress((void**)&p_kh, g_kh);
    cudaGetSymbolAddress((void**)&p_vh, g_vh);

    cudaMemcpyAsync(p_h, emb, sizeof(float) * (size_t)NTOK * DD,
                    cudaMemcpyDeviceToDevice);

    // weight conversion: 4 launches, native [K][N] layout, fully coalesced
    conv_qkv  <<<dim3(2048, LL), 256>>>(wq, wk, wv, p_wt + W1_QKV);
    conv_plain<<<dim3(1024, LL), 256>>>(wo, p_wt + W1_WO, 262144,
                                        (size_t)1048576, (size_t)W1_LAYER);
    conv_gu   <<<dim3(3072, LL), 256>>>(wg, wu, p_wt + W1_GU);
    conv_plain<<<dim3(3072, LL), 256>>>(wd, p_wt + W1_DN, 786432,
                                        (size_t)3145728, (size_t)W1_LAYER);

    for(int l = 0; l < LL; l++){
        __half* wb = p_wt + (size_t)l * W1_LAYER;
        rmsnorm_k<1><<<NTOK, 256>>>(p_h, ln1 + (size_t)l * DD, nullptr, p_nh);
        gemm_mma<0,2><<<dim3(16, 32), 256>>>(p_nh, wb + W1_QKV, 2048, nullptr,
            nullptr, 1024, 2048, qnw + (size_t)l * HDD, knw + (size_t)l * HDD,
            p_qh, p_kh, p_vh);
        attn_mma<<<dim3(SS / 64, HH, Bb), 128>>>(am, (l % 2 == 0) ? SS : WIN_, p_ch);
        gemm_mma<1,0><<<dim3(8, 32), 256>>>(p_ch, wb + W1_WO, 1024, p_h, nullptr,
            1024, 1024, nullptr, nullptr, nullptr, nullptr, nullptr);
        rmsnorm_k<1><<<NTOK, 256>>>(p_h, ln2 + (size_t)l * DD, nullptr, p_nh);
        gemm_mma<0,1><<<dim3(48, 32), 256>>>(p_nh, wb + W1_GU, 6144, nullptr, p_ah,
            1024, 6144, nullptr, nullptr, nullptr, nullptr, nullptr);
        gemm_mma<1,0><<<dim3(8, 32), 256>>>(p_ah, wb + W1_DN, 1024, p_h, nullptr,
            3072, 1024, nullptr, nullptr, nullptr, nullptr, nullptr);
    }
    rmsnorm_k<0><<<NTOK, 256>>>(p_h, nw, (float*)d_out, nullptr);
}